// round 14
// baseline (speedup 1.0000x reference)
#include <cuda_runtime.h>
#include <cuda_fp16.h>
#include <cstdint>

#define NQ 8192

__device__ __half g_qmh[NQ * 64];
__device__ __half g_qvh[NQ * 96];
__device__ __half g_Xmh[NQ * 64];
__device__ __half g_Xvh[NQ * 96];
__device__ float g_eqm[NQ], g_eqv[NQ], g_exnm[NQ], g_exnv[NQ];
__device__ float g_L[2][NQ * 32];
__device__ __half g_ZTh[2][32 * NQ], g_ZTl[2][32 * NQ];
__device__ __half g_LTh[2][32 * NQ], g_LTl[2][32 * NQ];
__device__ int g_cnt[2 * 64];

__device__ __forceinline__ uint32_t sm_u32(const void* p) {
    uint32_t a;
    asm("{ .reg .u64 t; cvta.to.shared.u64 t, %1; cvt.u32.u64 %0, t; }" : "=r"(a) : "l"(p));
    return a;
}
__device__ __forceinline__ void cp16(uint32_t d, const void* s) {
    asm volatile("cp.async.cg.shared.global [%0], [%1], 16;" :: "r"(d), "l"(s) : "memory");
}
#define CPC() asm volatile("cp.async.commit_group;" ::: "memory")
#define CPW(n) asm volatile("cp.async.wait_group %0;" :: "n"(n) : "memory")

__device__ __forceinline__ void mma16(float* c, const uint32_t* a, const uint32_t* b) {
    asm volatile(
        "mma.sync.aligned.m16n8k16.row.col.f32.f16.f16.f32 "
        "{%0,%1,%2,%3},{%4,%5,%6,%7},{%8,%9},{%0,%1,%2,%3};"
        : "+f"(c[0]), "+f"(c[1]), "+f"(c[2]), "+f"(c[3])
        : "r"(a[0]), "r"(a[1]), "r"(a[2]), "r"(a[3]), "r"(b[0]), "r"(b[1]));
}
#define LDSM4(r, addr) \
    asm volatile("ldmatrix.sync.aligned.m8n8.x4.shared.b16 {%0,%1,%2,%3}, [%4];" \
        : "=r"((r)[0]), "=r"((r)[1]), "=r"((r)[2]), "=r"((r)[3]) : "r"(addr))

__device__ __forceinline__ __half2 splitHi(float x, float y) {
    return __halves2half2(__float2half(x), __float2half(y));
}
__device__ __forceinline__ __half2 splitLo(float x, float y) {
    float hx = __half2float(__float2half(x)), hy = __half2float(__float2half(y));
    return __halves2half2(__float2half((x - hx) * 1024.0f),
                          __float2half((y - hy) * 1024.0f));
}
__device__ __forceinline__ uint32_t packh(float x, float y) {
    __half2 h = __halves2half2(__float2half(x), __float2half(y));
    return *reinterpret_cast<uint32_t*>(&h);
}

// ---------------- fused prep: 4 sections of 1024 blocks ----------------
__global__ __launch_bounds__(256) void prep_all(
    const float* __restrict__ x_mu, const float* __restrict__ y_eta,
    const float* __restrict__ y_mean, const float* __restrict__ y_var,
    const float* __restrict__ X_mean, const float* __restrict__ X_var,
    const float* __restrict__ Zm, const float* __restrict__ Zv,
    float* __restrict__ out)
{
    int sec = blockIdx.x >> 10, bx = blockIdx.x & 1023;
    int lane = threadIdx.x & 31;
    if (sec == 0) {
        int q = bx * 8 + (threadIdx.x >> 5);
        float a = x_mu[q * 32 + lane];
        float s = y_mean[q * 32 + lane] + y_var[q * 32 + lane];
        float e = 0.01f * y_eta[(NQ - 1 - q) * 32 + lane];
        g_qmh[q * 64 + lane] = __float2half(a);
        g_qmh[q * 64 + 32 + lane] = __float2half(s);
        g_qvh[q * 96 + lane] = __float2half(a);
        g_qvh[q * 96 + 32 + lane] = __float2half(e);
        g_qvh[q * 96 + 64 + lane] = __float2half(s);
        out[q * 32 + lane] = s;
        float nm = a * a + s * s, nv = nm + e * e;
#pragma unroll
        for (int o = 16; o > 0; o >>= 1) {
            nm += __shfl_xor_sync(~0u, nm, o);
            nv += __shfl_xor_sync(~0u, nv, o);
        }
        if (lane == 0) {
            g_eqm[q] = __expf(-nm * 0.0078125f);
            g_eqv[q] = __expf(-nv * 0.0078125f);
        }
    } else if (sec == 1) {
        int n = bx * 8 + (threadIdx.x >> 5);
        float acc = 0.0f;
#pragma unroll
        for (int d = 0; d < 64; d += 32) {
            float v = X_mean[(size_t)n * 64 + d + lane];
            g_Xmh[(size_t)n * 64 + d + lane] = __float2half(v);
            acc = fmaf(v, v, acc);
        }
#pragma unroll
        for (int o = 16; o > 0; o >>= 1) acc += __shfl_xor_sync(~0u, acc, o);
        if (lane == 0) g_exnm[n] = __expf(-acc * 0.0078125f);
    } else if (sec == 2) {
        int n = bx * 8 + (threadIdx.x >> 5);
        float acc = 0.0f;
#pragma unroll
        for (int d = 0; d < 96; d += 32) {
            float v = X_var[(size_t)n * 96 + d + lane];
            g_Xvh[(size_t)n * 96 + d + lane] = __float2half(v);
            acc = fmaf(v, v, acc);
        }
#pragma unroll
        for (int o = 16; o > 0; o >>= 1) acc += __shfl_xor_sync(~0u, acc, o);
        if (lane == 0) g_exnv[n] = __expf(-acc * 0.0078125f);
    } else {
        int o = bx * 256 + threadIdx.x;
        int j = o >> 13, n = o & (NQ - 1);
        float zm = Zm[n * 32 + j], zv = Zv[n * 32 + j];
        g_ZTh[0][o] = __low2half(splitHi(zm, zm)); g_ZTl[0][o] = __low2half(splitLo(zm, zm));
        g_ZTh[1][o] = __low2half(splitHi(zv, zv)); g_ZTl[1][o] = __low2half(splitLo(zv, zv));
        g_L[0][o] = 0.0f; g_L[1][o] = 0.0f;
        if (bx == 0 && threadIdx.x < 128) g_cnt[threadIdx.x] = 0;
    }
}

// ---------------- Stage A: Lambda = kXX_inv @ Z; last k-split CTA scales+splits ----------------
template <int V>
__device__ __forceinline__ void stageA_body(char* smA, const float* __restrict__ A)
{
    float*  sAf = (float*)smA;                           // [2][128*36]
    __half* sAh = (__half*)(smA + 36864);                // [2][128*40]
    __half* sZh = (__half*)(smA + 36864 + 20480);        // [2][32*40]
    __half* sZl = sZh + 2 * 32 * 40;
    int tid = threadIdx.x, wid = tid >> 5, lane = tid & 31;
    int g = lane >> 2, kq = lane & 3;
    size_t r0 = (size_t)blockIdx.x * 128;
    int kb = blockIdx.y * 2048;
    uint32_t aAf = sm_u32(sAf), aZh = sm_u32(sZh), aZl = sm_u32(sZl);

    auto load = [&](int c) {
        int b = c & 1, kc = kb + c * 32;
#pragma unroll
        for (int t = 0; t < 4; t++) {
            int f = tid + 256 * t, r = f >> 3, kg = f & 7;
            cp16(aAf + (b * 128 * 36 + r * 36 + kg * 4) * 4,
                 A + (r0 + r) * NQ + kc + kg * 4);
        }
        {
            int h = tid >> 7, rem = tid & 127, j = rem >> 2, kg = rem & 3;
            const __half* src = h ? g_ZTl[V] : g_ZTh[V];
            cp16((h ? aZl : aZh) + (b * 32 * 40 + j * 40 + kg * 8) * 2,
                 src + (size_t)j * NQ + kc + kg * 8);
        }
        CPC();
    };
    load(0);

    float accH[4][4], accL[4][4];
#pragma unroll
    for (int i = 0; i < 4; i++)
#pragma unroll
        for (int j = 0; j < 4; j++) { accH[i][j] = 0.0f; accL[i][j] = 0.0f; }

    for (int c = 0; c < 64; c++) {
        int b = c & 1;
        if (c + 1 < 64) { load(c + 1); CPW(1); } else CPW(0);
        __syncthreads();
#pragma unroll
        for (int t = 0; t < 8; t++) {
            int idx = tid + 256 * t;
            int r = idx >> 4, kp = idx & 15;
            float2 v = *(float2*)&sAf[b * 128 * 36 + r * 36 + kp * 2];
            *(__half2*)&sAh[b * 128 * 40 + r * 40 + kp * 2] = splitHi(v.x, v.y);
        }
        __syncthreads();
        const __half* pAh = sAh + b * 128 * 40;
        const __half* pZh = sZh + b * 32 * 40;
        const __half* pZl = sZl + b * 32 * 40;
        int rA = wid * 16 + g;
#pragma unroll
        for (int ks = 0; ks < 2; ks++) {
            int ko = ks * 16 + 2 * kq;
            uint32_t ah[4];
            ah[0] = *(const uint32_t*)&pAh[rA * 40 + ko];
            ah[1] = *(const uint32_t*)&pAh[(rA + 8) * 40 + ko];
            ah[2] = *(const uint32_t*)&pAh[rA * 40 + ko + 8];
            ah[3] = *(const uint32_t*)&pAh[(rA + 8) * 40 + ko + 8];
#pragma unroll
            for (int nt = 0; nt < 4; nt++) {
                int rB = nt * 8 + g;
                uint32_t bh[2], bl[2];
                bh[0] = *(const uint32_t*)&pZh[rB * 40 + ko];
                bh[1] = *(const uint32_t*)&pZh[rB * 40 + ko + 8];
                bl[0] = *(const uint32_t*)&pZl[rB * 40 + ko];
                bl[1] = *(const uint32_t*)&pZl[rB * 40 + ko + 8];
                mma16(accH[nt], ah, bh);
                mma16(accL[nt], ah, bl);
            }
        }
        __syncthreads();
    }
    float* L = g_L[V];
    size_t ra = r0 + wid * 16 + g;
#pragma unroll
    for (int nt = 0; nt < 4; nt++) {
        int col = nt * 8 + 2 * kq;
        atomicAdd(&L[ra * 32 + col],           accH[nt][0] + accL[nt][0] * 9.765625e-4f);
        atomicAdd(&L[ra * 32 + col + 1],       accH[nt][1] + accL[nt][1] * 9.765625e-4f);
        atomicAdd(&L[(ra + 8) * 32 + col],     accH[nt][2] + accL[nt][2] * 9.765625e-4f);
        atomicAdd(&L[(ra + 8) * 32 + col + 1], accH[nt][3] + accL[nt][3] * 9.765625e-4f);
    }

    // last k-split CTA for this rowblock scales Lambda by exn and writes hi/lo splits
    __shared__ int sLast;
    __threadfence();
    __syncthreads();
    if (tid == 0) sLast = (atomicAdd(&g_cnt[V * 64 + blockIdx.x], 1) == 3);
    __syncthreads();
    if (sLast) {
        const float* exn = V ? g_exnv : g_exnm;
        __half* LTh = g_LTh[V];
        __half* LTl = g_LTl[V];
        for (int o = tid; o < 4096; o += 256) {
            int nl = o >> 5, j = o & 31;
            size_t n = r0 + nl;
            float v = __ldcg(&L[n * 32 + j]) * exn[n];
            __half h = __float2half(v);
            LTh[(size_t)j * NQ + n] = h;
            LTl[(size_t)j * NQ + n] = __float2half((v - __half2float(h)) * 1024.0f);
        }
    }
}

__global__ __launch_bounds__(256, 2) void stageA_all(
    const float* __restrict__ A0, const float* __restrict__ A1)
{
    extern __shared__ char smA[];
    if (blockIdx.z == 0) stageA_body<0>(smA, A0);
    else                 stageA_body<1>(smA, A1);
}

// ---------------- Stage B: fused RBF + z (R12 loop, lo folded into zH) ----------------
template <int D, int V>
__device__ __forceinline__ void stageB_body(__half* smB, float* __restrict__ out)
{
    const __half* Qg = V ? g_qvh : g_qmh;
    const __half* Xg = V ? g_Xvh : g_Xmh;
    const float*  EQ = V ? g_eqv : g_eqm;
    const int SP = D + 8;
    __half* sQ  = smB;                    // [128][SP]
    __half* sX  = sQ + 128 * SP;          // [2][64][SP]
    __half* sLh = sX + 2 * 64 * SP;       // [2][32 j][72 n]
    __half* sLl = sLh + 2 * 32 * 72;
    uint32_t aQ = sm_u32(sQ), aX = sm_u32(sX), aLh = sm_u32(sLh), aLl = sm_u32(sLl);
    int tid = threadIdx.x, wid = tid >> 5, lane = tid & 31;
    int g = lane >> 2, kq = lane & 3;
    int wm = wid >> 1, wn = wid & 1;
    int q0 = blockIdx.x * 128, nb = blockIdx.y * 2048;
    const int NC = 32;
    const int XB = 64 * SP * 2, LB = 32 * 72 * 2;

    int m = lane >> 3, lr = lane & 7;
    uint32_t adrQ[2], adrX[2], adrLh[2], adrLl[2];
#pragma unroll
    for (int mt = 0; mt < 2; mt++) {
        int row = wm * 32 + mt * 16 + (m & 1) * 8 + lr;
        adrQ[mt] = aQ + (row * SP) * 2 + (m >> 1) * 16;
    }
#pragma unroll
    for (int p = 0; p < 2; p++) {
        int n = wn * 32 + (2 * p + (m >> 1)) * 8 + lr;
        adrX[p] = aX + (n * SP) * 2 + (m & 1) * 16;
        int j = (2 * p + (m >> 1)) * 8 + lr;
        uint32_t off = (j * 72) * 2 + wn * 64 + (m & 1) * 16;
        adrLh[p] = aLh + off;
        adrLl[p] = aLl + off;
    }

    for (int idx = tid; idx < 128 * (D / 8); idx += 256) {
        int r = idx / (D / 8), kg = idx % (D / 8);
        cp16(aQ + (r * SP + kg * 8) * 2, Qg + (size_t)(q0 + r) * D + kg * 8);
    }
    auto loadC = [&](int c) {
        int b = c & 1, n0 = nb + c * 64;
        for (int idx = tid; idx < 64 * (D / 8); idx += 256) {
            int r = idx / (D / 8), kg = idx % (D / 8);
            cp16(aX + b * XB + (r * SP + kg * 8) * 2,
                 Xg + (size_t)(n0 + r) * D + kg * 8);
        }
#pragma unroll
        for (int t = 0; t < 2; t++) {
            int f = tid + 256 * t;
            int h = f >> 8, rem = f & 255, j = rem >> 3, kg = rem & 7;
            const __half* src = h ? g_LTl[V] : g_LTh[V];
            cp16((h ? aLl : aLh) + b * LB + (j * 72 + kg * 8) * 2,
                 src + (size_t)j * NQ + n0 + kg * 8);
        }
        CPC();
    };
    loadC(0);

    float zH[2][4][4];
#pragma unroll
    for (int mm = 0; mm < 2; mm++)
#pragma unroll
        for (int i = 0; i < 4; i++)
#pragma unroll
            for (int j = 0; j < 4; j++) zH[mm][i][j] = 0.0f;

    const float S10 = 9.765625e-4f;   // 2^-10

    for (int c = 0; c < NC; c++) {
        int b = c & 1;
        if (c + 1 < NC) { loadC(c + 1); CPW(1); } else CPW(0);
        __syncthreads();

        // mma1: S = Q . X^T for this warp's 32q x 32n tile
        float s[2][4][4];
#pragma unroll
        for (int mt = 0; mt < 2; mt++)
#pragma unroll
            for (int nt = 0; nt < 4; nt++)
#pragma unroll
                for (int i = 0; i < 4; i++) s[mt][nt][i] = 0.0f;
#pragma unroll
        for (int ks = 0; ks < D / 16; ks++) {
            uint32_t a2[2][4], bb[2][4];
            LDSM4(a2[0], adrQ[0] + ks * 32);
            LDSM4(a2[1], adrQ[1] + ks * 32);
            LDSM4(bb[0], adrX[0] + b * XB + ks * 32);
            LDSM4(bb[1], adrX[1] + b * XB + ks * 32);
#pragma unroll
            for (int p = 0; p < 2; p++) {
                mma16(s[0][2 * p],     a2[0], &bb[p][0]);
                mma16(s[0][2 * p + 1], a2[0], &bb[p][2]);
                mma16(s[1][2 * p],     a2[1], &bb[p][0]);
                mma16(s[1][2 * p + 1], a2[1], &bb[p][2]);
            }
        }
        // K = exp(S/64); pack hi and scaled-lo A-fragments (k = n dim)
        uint32_t kh[2][2][4], kl[2][2][4];
#pragma unroll
        for (int mt = 0; mt < 2; mt++)
#pragma unroll
            for (int nt = 0; nt < 4; nt++)
#pragma unroll
                for (int i = 0; i < 4; i++)
                    s[mt][nt][i] = __expf(s[mt][nt][i] * 0.015625f);
#pragma unroll
        for (int mt = 0; mt < 2; mt++)
#pragma unroll
            for (int ks = 0; ks < 2; ks++) {
                kh[mt][ks][0] = packh(s[mt][2 * ks][0],     s[mt][2 * ks][1]);
                kh[mt][ks][1] = packh(s[mt][2 * ks][2],     s[mt][2 * ks][3]);
                kh[mt][ks][2] = packh(s[mt][2 * ks + 1][0], s[mt][2 * ks + 1][1]);
                kh[mt][ks][3] = packh(s[mt][2 * ks + 1][2], s[mt][2 * ks + 1][3]);
                kl[mt][ks][0] = packh(s[mt][2 * ks][0] * S10,     s[mt][2 * ks][1] * S10);
                kl[mt][ks][1] = packh(s[mt][2 * ks][2] * S10,     s[mt][2 * ks][3] * S10);
                kl[mt][ks][2] = packh(s[mt][2 * ks + 1][0] * S10, s[mt][2 * ks + 1][1] * S10);
                kl[mt][ks][3] = packh(s[mt][2 * ks + 1][2] * S10, s[mt][2 * ks + 1][3] * S10);
            }

        // mma2: z += K . Lam'^T over this warp's 32-n slice (hi + lo into zH)
#pragma unroll
        for (int ks = 0; ks < 2; ks++) {
            uint32_t bh[2][4], bl[2][4];
            LDSM4(bh[0], adrLh[0] + b * LB + ks * 32);
            LDSM4(bh[1], adrLh[1] + b * LB + ks * 32);
            LDSM4(bl[0], adrLl[0] + b * LB + ks * 32);
            LDSM4(bl[1], adrLl[1] + b * LB + ks * 32);
#pragma unroll
            for (int jt = 0; jt < 4; jt++) {
                int jp = jt >> 1, ji = (jt & 1) * 2;
                mma16(zH[0][jt], kh[0][ks], &bh[jp][ji]);
                mma16(zH[0][jt], kl[0][ks], &bl[jp][ji]);
                mma16(zH[1][jt], kh[1][ks], &bh[jp][ji]);
                mma16(zH[1][jt], kl[1][ks], &bl[jp][ji]);
            }
        }
        __syncthreads();
    }
#pragma unroll
    for (int mt = 0; mt < 2; mt++) {
        int qa = q0 + wm * 32 + mt * 16 + g;
        float e0 = EQ[qa], e1 = EQ[qa + 8];
#pragma unroll
        for (int jt = 0; jt < 4; jt++) {
            int col = jt * 8 + 2 * kq;
            atomicAdd(&out[qa * 32 + col],           e0 * zH[mt][jt][0]);
            atomicAdd(&out[qa * 32 + col + 1],       e0 * zH[mt][jt][1]);
            atomicAdd(&out[(qa + 8) * 32 + col],     e1 * zH[mt][jt][2]);
            atomicAdd(&out[(qa + 8) * 32 + col + 1], e1 * zH[mt][jt][3]);
        }
    }
}

__global__ __launch_bounds__(256, 2) void stageB_all(float* __restrict__ out)
{
    extern __shared__ __half smB[];
    if (blockIdx.z == 0) stageB_body<64, 0>(smB, out);
    else                 stageB_body<96, 1>(smB, out);
}

// ---------------- launch ----------------
extern "C" void kernel_launch(void* const* d_in, const int* in_sizes, int n_in,
                              void* d_out, int out_size)
{
    const float* x_mu   = (const float*)d_in[0];
    const float* y_eta  = (const float*)d_in[1];
    const float* y_mean = (const float*)d_in[2];
    const float* y_var  = (const float*)d_in[3];
    const float* X_mean = (const float*)d_in[4];
    const float* X_var  = (const float*)d_in[5];
    const float* Z_mean = (const float*)d_in[6];
    const float* Z_var  = (const float*)d_in[7];
    const float* kXXm   = (const float*)d_in[8];
    const float* kXXv   = (const float*)d_in[9];
    float* out = (float*)d_out;

    const int SMA  = 36864 + 20480 + 2 * 5120;                         // 67584
    const int SMB  = (128 * 104 + 2 * 64 * 104 + 4 * 32 * 72) * 2;     // 71680 (D=96 layout)
    cudaFuncSetAttribute(stageA_all, cudaFuncAttributeMaxDynamicSharedMemorySize, SMA);
    cudaFuncSetAttribute(stageB_all, cudaFuncAttributeMaxDynamicSharedMemorySize, SMB);

    prep_all<<<4096, 256>>>(x_mu, y_eta, y_mean, y_var, X_mean, X_var,
                            Z_mean, Z_var, out);

    stageA_all<<<dim3(64, 4, 2), 256, SMA>>>(kXXm, kXXv);

    stageB_all<<<dim3(64, 4, 2), 256, SMB>>>(out);
}

// round 15
// speedup vs baseline: 1.0214x; 1.0214x over previous
#include <cuda_runtime.h>
#include <cuda_fp16.h>
#include <cstdint>

#define NQ 8192

__device__ __half g_qmh[NQ * 64];
__device__ __half g_qvh[NQ * 96];
__device__ __half g_Xmh[NQ * 64];
__device__ __half g_Xvh[NQ * 96];
__device__ float g_eqm[NQ], g_eqv[NQ], g_exnm[NQ], g_exnv[NQ];
__device__ float g_L[2][NQ * 32];
__device__ __half g_ZTh[2][32 * NQ], g_ZTl[2][32 * NQ];
__device__ __half g_LTh[2][32 * NQ], g_LTl[2][32 * NQ];

__device__ __forceinline__ uint32_t sm_u32(const void* p) {
    uint32_t a;
    asm("{ .reg .u64 t; cvta.to.shared.u64 t, %1; cvt.u32.u64 %0, t; }" : "=r"(a) : "l"(p));
    return a;
}
__device__ __forceinline__ void cp16(uint32_t d, const void* s) {
    asm volatile("cp.async.cg.shared.global [%0], [%1], 16;" :: "r"(d), "l"(s) : "memory");
}
#define CPC() asm volatile("cp.async.commit_group;" ::: "memory")
#define CPW(n) asm volatile("cp.async.wait_group %0;" :: "n"(n) : "memory")

__device__ __forceinline__ void mma16(float* c, const uint32_t* a, const uint32_t* b) {
    asm volatile(
        "mma.sync.aligned.m16n8k16.row.col.f32.f16.f16.f32 "
        "{%0,%1,%2,%3},{%4,%5,%6,%7},{%8,%9},{%0,%1,%2,%3};"
        : "+f"(c[0]), "+f"(c[1]), "+f"(c[2]), "+f"(c[3])
        : "r"(a[0]), "r"(a[1]), "r"(a[2]), "r"(a[3]), "r"(b[0]), "r"(b[1]));
}
#define LDSM4(r, addr) \
    asm volatile("ldmatrix.sync.aligned.m8n8.x4.shared.b16 {%0,%1,%2,%3}, [%4];" \
        : "=r"((r)[0]), "=r"((r)[1]), "=r"((r)[2]), "=r"((r)[3]) : "r"(addr))

__device__ __forceinline__ __half2 splitHi(float x, float y) {
    return __halves2half2(__float2half(x), __float2half(y));
}
__device__ __forceinline__ __half2 splitLo(float x, float y) {
    float hx = __half2float(__float2half(x)), hy = __half2float(__float2half(y));
    return __halves2half2(__float2half((x - hx) * 1024.0f),
                          __float2half((y - hy) * 1024.0f));
}
__device__ __forceinline__ uint32_t packh(float x, float y) {
    __half2 h = __halves2half2(__float2half(x), __float2half(y));
    return *reinterpret_cast<uint32_t*>(&h);
}

// ---------------- fused prep: 4 sections of 1024 blocks ----------------
__global__ __launch_bounds__(256) void prep_all(
    const float* __restrict__ x_mu, const float* __restrict__ y_eta,
    const float* __restrict__ y_mean, const float* __restrict__ y_var,
    const float* __restrict__ X_mean, const float* __restrict__ X_var,
    const float* __restrict__ Zm, const float* __restrict__ Zv,
    float* __restrict__ out)
{
    int sec = blockIdx.x >> 10, bx = blockIdx.x & 1023;
    int lane = threadIdx.x & 31;
    if (sec == 0) {
        int q = bx * 8 + (threadIdx.x >> 5);
        float a = x_mu[q * 32 + lane];
        float s = y_mean[q * 32 + lane] + y_var[q * 32 + lane];
        float e = 0.01f * y_eta[(NQ - 1 - q) * 32 + lane];
        g_qmh[q * 64 + lane] = __float2half(a);
        g_qmh[q * 64 + 32 + lane] = __float2half(s);
        g_qvh[q * 96 + lane] = __float2half(a);
        g_qvh[q * 96 + 32 + lane] = __float2half(e);
        g_qvh[q * 96 + 64 + lane] = __float2half(s);
        out[q * 32 + lane] = s;
        float nm = a * a + s * s, nv = nm + e * e;
#pragma unroll
        for (int o = 16; o > 0; o >>= 1) {
            nm += __shfl_xor_sync(~0u, nm, o);
            nv += __shfl_xor_sync(~0u, nv, o);
        }
        if (lane == 0) {
            g_eqm[q] = __expf(-nm * 0.0078125f);
            g_eqv[q] = __expf(-nv * 0.0078125f);
        }
    } else if (sec == 1) {
        int n = bx * 8 + (threadIdx.x >> 5);
        float acc = 0.0f;
#pragma unroll
        for (int d = 0; d < 64; d += 32) {
            float v = X_mean[(size_t)n * 64 + d + lane];
            g_Xmh[(size_t)n * 64 + d + lane] = __float2half(v);
            acc = fmaf(v, v, acc);
        }
#pragma unroll
        for (int o = 16; o > 0; o >>= 1) acc += __shfl_xor_sync(~0u, acc, o);
        if (lane == 0) g_exnm[n] = __expf(-acc * 0.0078125f);
    } else if (sec == 2) {
        int n = bx * 8 + (threadIdx.x >> 5);
        float acc = 0.0f;
#pragma unroll
        for (int d = 0; d < 96; d += 32) {
            float v = X_var[(size_t)n * 96 + d + lane];
            g_Xvh[(size_t)n * 96 + d + lane] = __float2half(v);
            acc = fmaf(v, v, acc);
        }
#pragma unroll
        for (int o = 16; o > 0; o >>= 1) acc += __shfl_xor_sync(~0u, acc, o);
        if (lane == 0) g_exnv[n] = __expf(-acc * 0.0078125f);
    } else {
        int o = bx * 256 + threadIdx.x;
        int j = o >> 13, n = o & (NQ - 1);
        float zm = Zm[n * 32 + j], zv = Zv[n * 32 + j];
        g_ZTh[0][o] = __low2half(splitHi(zm, zm)); g_ZTl[0][o] = __low2half(splitLo(zm, zm));
        g_ZTh[1][o] = __low2half(splitHi(zv, zv)); g_ZTl[1][o] = __low2half(splitLo(zv, zv));
        g_L[0][o] = 0.0f; g_L[1][o] = 0.0f;
    }
}

__global__ __launch_bounds__(256) void scaleL()
{
    int o = blockIdx.x * 256 + threadIdx.x;
    int j = o >> 13, n = o & (NQ - 1);
    float a = g_L[0][n * 32 + j] * g_exnm[n];
    float b = g_L[1][n * 32 + j] * g_exnv[n];
    g_LTh[0][o] = __low2half(splitHi(a, a)); g_LTl[0][o] = __low2half(splitLo(a, a));
    g_LTh[1][o] = __low2half(splitHi(b, b)); g_LTl[1][o] = __low2half(splitLo(b, b));
}

// ---------------- Stage A: Lambda = kXX_inv @ Z  (fp16 2-term: Ah*(Zh+Zl)) ----------------
template <int V>
__global__ __launch_bounds__(256, 2) void stageA(const float* __restrict__ A)
{
    extern __shared__ char smA[];
    float*  sAf = (float*)smA;                           // [2][128*36]
    __half* sAh = (__half*)(smA + 36864);                // [2][128*40]
    __half* sZh = (__half*)(smA + 36864 + 20480);        // [2][32*40]
    __half* sZl = sZh + 2 * 32 * 40;
    int tid = threadIdx.x, wid = tid >> 5, lane = tid & 31;
    int g = lane >> 2, kq = lane & 3;
    size_t r0 = (size_t)blockIdx.x * 128;
    int kb = blockIdx.y * 2048;
    uint32_t aAf = sm_u32(sAf), aZh = sm_u32(sZh), aZl = sm_u32(sZl);

    auto load = [&](int c) {
        int b = c & 1, kc = kb + c * 32;
#pragma unroll
        for (int t = 0; t < 4; t++) {
            int f = tid + 256 * t, r = f >> 3, kg = f & 7;
            cp16(aAf + (b * 128 * 36 + r * 36 + kg * 4) * 4,
                 A + (r0 + r) * NQ + kc + kg * 4);
        }
        {
            int h = tid >> 7, rem = tid & 127, j = rem >> 2, kg = rem & 3;
            const __half* src = h ? g_ZTl[V] : g_ZTh[V];
            cp16((h ? aZl : aZh) + (b * 32 * 40 + j * 40 + kg * 8) * 2,
                 src + (size_t)j * NQ + kc + kg * 8);
        }
        CPC();
    };
    load(0);

    float accH[4][4], accL[4][4];
#pragma unroll
    for (int i = 0; i < 4; i++)
#pragma unroll
        for (int j = 0; j < 4; j++) { accH[i][j] = 0.0f; accL[i][j] = 0.0f; }

    for (int c = 0; c < 64; c++) {
        int b = c & 1;
        if (c + 1 < 64) { load(c + 1); CPW(1); } else CPW(0);
        __syncthreads();
#pragma unroll
        for (int t = 0; t < 8; t++) {
            int idx = tid + 256 * t;
            int r = idx >> 4, kp = idx & 15;
            float2 v = *(float2*)&sAf[b * 128 * 36 + r * 36 + kp * 2];
            *(__half2*)&sAh[b * 128 * 40 + r * 40 + kp * 2] = splitHi(v.x, v.y);
        }
        __syncthreads();
        const __half* pAh = sAh + b * 128 * 40;
        const __half* pZh = sZh + b * 32 * 40;
        const __half* pZl = sZl + b * 32 * 40;
        int rA = wid * 16 + g;
#pragma unroll
        for (int ks = 0; ks < 2; ks++) {
            int ko = ks * 16 + 2 * kq;
            uint32_t ah[4];
            ah[0] = *(const uint32_t*)&pAh[rA * 40 + ko];
            ah[1] = *(const uint32_t*)&pAh[(rA + 8) * 40 + ko];
            ah[2] = *(const uint32_t*)&pAh[rA * 40 + ko + 8];
            ah[3] = *(const uint32_t*)&pAh[(rA + 8) * 40 + ko + 8];
#pragma unroll
            for (int nt = 0; nt < 4; nt++) {
                int rB = nt * 8 + g;
                uint32_t bh[2], bl[2];
                bh[0] = *(const uint32_t*)&pZh[rB * 40 + ko];
                bh[1] = *(const uint32_t*)&pZh[rB * 40 + ko + 8];
                bl[0] = *(const uint32_t*)&pZl[rB * 40 + ko];
                bl[1] = *(const uint32_t*)&pZl[rB * 40 + ko + 8];
                mma16(accH[nt], ah, bh);
                mma16(accL[nt], ah, bl);
            }
        }
        __syncthreads();
    }
    float* L = g_L[V];
    size_t ra = r0 + wid * 16 + g;
#pragma unroll
    for (int nt = 0; nt < 4; nt++) {
        int col = nt * 8 + 2 * kq;
        atomicAdd(&L[ra * 32 + col],           accH[nt][0] + accL[nt][0] * 9.765625e-4f);
        atomicAdd(&L[ra * 32 + col + 1],       accH[nt][1] + accL[nt][1] * 9.765625e-4f);
        atomicAdd(&L[(ra + 8) * 32 + col],     accH[nt][2] + accL[nt][2] * 9.765625e-4f);
        atomicAdd(&L[(ra + 8) * 32 + col + 1], accH[nt][3] + accL[nt][3] * 9.765625e-4f);
    }
}

// ---------------- Stage B: fused RBF + z (R12 loop, zL folded into zH) ----------------
// grid (64 q-tiles x 128, 4 n-splits x 2048), block 256, occ 2, 32 chunks of 64 n.
template <int D, int V>
__global__ __launch_bounds__(256, 2) void stageB(float* __restrict__ out)
{
    const __half* Qg = V ? g_qvh : g_qmh;
    const __half* Xg = V ? g_Xvh : g_Xmh;
    const float*  EQ = V ? g_eqv : g_eqm;
    extern __shared__ __half smB[];
    const int SP = D + 8;
    __half* sQ  = smB;                    // [128][SP]
    __half* sX  = sQ + 128 * SP;          // [2][64][SP]
    __half* sLh = sX + 2 * 64 * SP;       // [2][32 j][72 n]
    __half* sLl = sLh + 2 * 32 * 72;
    uint32_t aQ = sm_u32(sQ), aX = sm_u32(sX), aLh = sm_u32(sLh), aLl = sm_u32(sLl);
    int tid = threadIdx.x, wid = tid >> 5, lane = tid & 31;
    int g = lane >> 2, kq = lane & 3;
    int wm = wid >> 1, wn = wid & 1;
    int q0 = blockIdx.x * 128, nb = blockIdx.y * 2048;
    const int NC = 32;
    const int XB = 64 * SP * 2, LB = 32 * 72 * 2;

    int m = lane >> 3, lr = lane & 7;
    uint32_t adrQ[2], adrX[2], adrLh[2], adrLl[2];
#pragma unroll
    for (int mt = 0; mt < 2; mt++) {
        int row = wm * 32 + mt * 16 + (m & 1) * 8 + lr;
        adrQ[mt] = aQ + (row * SP) * 2 + (m >> 1) * 16;
    }
#pragma unroll
    for (int p = 0; p < 2; p++) {
        int n = wn * 32 + (2 * p + (m >> 1)) * 8 + lr;
        adrX[p] = aX + (n * SP) * 2 + (m & 1) * 16;
        int j = (2 * p + (m >> 1)) * 8 + lr;
        uint32_t off = (j * 72) * 2 + wn * 64 + (m & 1) * 16;
        adrLh[p] = aLh + off;
        adrLl[p] = aLl + off;
    }

    for (int idx = tid; idx < 128 * (D / 8); idx += 256) {
        int r = idx / (D / 8), kg = idx % (D / 8);
        cp16(aQ + (r * SP + kg * 8) * 2, Qg + (size_t)(q0 + r) * D + kg * 8);
    }
    auto loadC = [&](int c) {
        int b = c & 1, n0 = nb + c * 64;
        for (int idx = tid; idx < 64 * (D / 8); idx += 256) {
            int r = idx / (D / 8), kg = idx % (D / 8);
            cp16(aX + b * XB + (r * SP + kg * 8) * 2,
                 Xg + (size_t)(n0 + r) * D + kg * 8);
        }
#pragma unroll
        for (int t = 0; t < 2; t++) {
            int f = tid + 256 * t;
            int h = f >> 8, rem = f & 255, j = rem >> 3, kg = rem & 7;
            const __half* src = h ? g_LTl[V] : g_LTh[V];
            cp16((h ? aLl : aLh) + b * LB + (j * 72 + kg * 8) * 2,
                 src + (size_t)j * NQ + n0 + kg * 8);
        }
        CPC();
    };
    loadC(0);

    float zH[2][4][4];
#pragma unroll
    for (int mm = 0; mm < 2; mm++)
#pragma unroll
        for (int i = 0; i < 4; i++)
#pragma unroll
            for (int j = 0; j < 4; j++) zH[mm][i][j] = 0.0f;

    const float S10 = 9.765625e-4f;   // 2^-10

    for (int c = 0; c < NC; c++) {
        int b = c & 1;
        if (c + 1 < NC) { loadC(c + 1); CPW(1); } else CPW(0);
        __syncthreads();

        // mma1: S = Q . X^T for this warp's 32q x 32n tile
        float s[2][4][4];
#pragma unroll
        for (int mt = 0; mt < 2; mt++)
#pragma unroll
            for (int nt = 0; nt < 4; nt++)
#pragma unroll
                for (int i = 0; i < 4; i++) s[mt][nt][i] = 0.0f;
#pragma unroll
        for (int ks = 0; ks < D / 16; ks++) {
            uint32_t a2[2][4], bb[2][4];
            LDSM4(a2[0], adrQ[0] + ks * 32);
            LDSM4(a2[1], adrQ[1] + ks * 32);
            LDSM4(bb[0], adrX[0] + b * XB + ks * 32);
            LDSM4(bb[1], adrX[1] + b * XB + ks * 32);
#pragma unroll
            for (int p = 0; p < 2; p++) {
                mma16(s[0][2 * p],     a2[0], &bb[p][0]);
                mma16(s[0][2 * p + 1], a2[0], &bb[p][2]);
                mma16(s[1][2 * p],     a2[1], &bb[p][0]);
                mma16(s[1][2 * p + 1], a2[1], &bb[p][2]);
            }
        }
        // K = exp(S/64); pack hi and scaled-lo A-fragments (k = n dim)
        uint32_t kh[2][2][4], kl[2][2][4];
#pragma unroll
        for (int mt = 0; mt < 2; mt++)
#pragma unroll
            for (int nt = 0; nt < 4; nt++)
#pragma unroll
                for (int i = 0; i < 4; i++)
                    s[mt][nt][i] = __expf(s[mt][nt][i] * 0.015625f);
#pragma unroll
        for (int mt = 0; mt < 2; mt++)
#pragma unroll
            for (int ks = 0; ks < 2; ks++) {
                kh[mt][ks][0] = packh(s[mt][2 * ks][0],     s[mt][2 * ks][1]);
                kh[mt][ks][1] = packh(s[mt][2 * ks][2],     s[mt][2 * ks][3]);
                kh[mt][ks][2] = packh(s[mt][2 * ks + 1][0], s[mt][2 * ks + 1][1]);
                kh[mt][ks][3] = packh(s[mt][2 * ks + 1][2], s[mt][2 * ks + 1][3]);
                kl[mt][ks][0] = packh(s[mt][2 * ks][0] * S10,     s[mt][2 * ks][1] * S10);
                kl[mt][ks][1] = packh(s[mt][2 * ks][2] * S10,     s[mt][2 * ks][3] * S10);
                kl[mt][ks][2] = packh(s[mt][2 * ks + 1][0] * S10, s[mt][2 * ks + 1][1] * S10);
                kl[mt][ks][3] = packh(s[mt][2 * ks + 1][2] * S10, s[mt][2 * ks + 1][3] * S10);
            }

        // mma2: z += K . Lam'^T over this warp's 32-n slice (hi + lo into zH)
#pragma unroll
        for (int ks = 0; ks < 2; ks++) {
            uint32_t bh[2][4], bl[2][4];
            LDSM4(bh[0], adrLh[0] + b * LB + ks * 32);
            LDSM4(bh[1], adrLh[1] + b * LB + ks * 32);
            LDSM4(bl[0], adrLl[0] + b * LB + ks * 32);
            LDSM4(bl[1], adrLl[1] + b * LB + ks * 32);
#pragma unroll
            for (int jt = 0; jt < 4; jt++) {
                int jp = jt >> 1, ji = (jt & 1) * 2;
                mma16(zH[0][jt], kh[0][ks], &bh[jp][ji]);
                mma16(zH[0][jt], kl[0][ks], &bl[jp][ji]);
                mma16(zH[1][jt], kh[1][ks], &bh[jp][ji]);
                mma16(zH[1][jt], kl[1][ks], &bl[jp][ji]);
            }
        }
        __syncthreads();
    }
#pragma unroll
    for (int mt = 0; mt < 2; mt++) {
        int qa = q0 + wm * 32 + mt * 16 + g;
        float e0 = EQ[qa], e1 = EQ[qa + 8];
#pragma unroll
        for (int jt = 0; jt < 4; jt++) {
            int col = jt * 8 + 2 * kq;
            atomicAdd(&out[qa * 32 + col],           e0 * zH[mt][jt][0]);
            atomicAdd(&out[qa * 32 + col + 1],       e0 * zH[mt][jt][1]);
            atomicAdd(&out[(qa + 8) * 32 + col],     e1 * zH[mt][jt][2]);
            atomicAdd(&out[(qa + 8) * 32 + col + 1], e1 * zH[mt][jt][3]);
        }
    }
}

// ---------------- launch ----------------
extern "C" void kernel_launch(void* const* d_in, const int* in_sizes, int n_in,
                              void* d_out, int out_size)
{
    const float* x_mu   = (const float*)d_in[0];
    const float* y_eta  = (const float*)d_in[1];
    const float* y_mean = (const float*)d_in[2];
    const float* y_var  = (const float*)d_in[3];
    const float* X_mean = (const float*)d_in[4];
    const float* X_var  = (const float*)d_in[5];
    const float* Z_mean = (const float*)d_in[6];
    const float* Z_var  = (const float*)d_in[7];
    const float* kXXm   = (const float*)d_in[8];
    const float* kXXv   = (const float*)d_in[9];
    float* out = (float*)d_out;

    const int SMA  = 36864 + 20480 + 2 * 5120;                         // 67584
    const int SMB0 = (128 * 72 + 2 * 64 * 72 + 4 * 32 * 72) * 2;       // 55296
    const int SMB1 = (128 * 104 + 2 * 64 * 104 + 4 * 32 * 72) * 2;     // 71680
    cudaFuncSetAttribute(stageA<0>, cudaFuncAttributeMaxDynamicSharedMemorySize, SMA);
    cudaFuncSetAttribute(stageA<1>, cudaFuncAttributeMaxDynamicSharedMemorySize, SMA);
    cudaFuncSetAttribute(stageB<64, 0>, cudaFuncAttributeMaxDynamicSharedMemorySize, SMB0);
    cudaFuncSetAttribute(stageB<96, 1>, cudaFuncAttributeMaxDynamicSharedMemorySize, SMB1);

    prep_all<<<4096, 256>>>(x_mu, y_eta, y_mean, y_var, X_mean, X_var,
                            Z_mean, Z_var, out);

    stageA<0><<<dim3(64, 4), 256, SMA>>>(kXXm);
    stageA<1><<<dim3(64, 4), 256, SMA>>>(kXXv);
    scaleL<<<1024, 256>>>();

    stageB<64, 0><<<dim3(64, 4), 256, SMB0>>>(out);
    stageB<96, 1><<<dim3(64, 4), 256, SMB1>>>(out);
}

// round 16
// speedup vs baseline: 1.0337x; 1.0121x over previous
#include <cuda_runtime.h>
#include <cuda_fp16.h>
#include <cstdint>

#define NQ 8192

__device__ __half g_qmh[NQ * 64];
__device__ __half g_qvh[NQ * 96];
__device__ __half g_Xmh[NQ * 64];
__device__ __half g_Xvh[NQ * 96];
__device__ float g_eqm[NQ], g_eqv[NQ], g_exnm[NQ], g_exnv[NQ];
__device__ float g_L[2][NQ * 32];
__device__ __half g_ZTh[2][32 * NQ], g_ZTl[2][32 * NQ];
__device__ __half g_LTh[2][32 * NQ], g_LTl[2][32 * NQ];

__device__ __forceinline__ uint32_t sm_u32(const void* p) {
    uint32_t a;
    asm("{ .reg .u64 t; cvta.to.shared.u64 t, %1; cvt.u32.u64 %0, t; }" : "=r"(a) : "l"(p));
    return a;
}
__device__ __forceinline__ void cp16(uint32_t d, const void* s) {
    asm volatile("cp.async.cg.shared.global [%0], [%1], 16;" :: "r"(d), "l"(s) : "memory");
}
#define CPC() asm volatile("cp.async.commit_group;" ::: "memory")
#define CPW(n) asm volatile("cp.async.wait_group %0;" :: "n"(n) : "memory")

__device__ __forceinline__ void mma16(float* c, const uint32_t* a, const uint32_t* b) {
    asm volatile(
        "mma.sync.aligned.m16n8k16.row.col.f32.f16.f16.f32 "
        "{%0,%1,%2,%3},{%4,%5,%6,%7},{%8,%9},{%0,%1,%2,%3};"
        : "+f"(c[0]), "+f"(c[1]), "+f"(c[2]), "+f"(c[3])
        : "r"(a[0]), "r"(a[1]), "r"(a[2]), "r"(a[3]), "r"(b[0]), "r"(b[1]));
}
#define LDSM4(r, addr) \
    asm volatile("ldmatrix.sync.aligned.m8n8.x4.shared.b16 {%0,%1,%2,%3}, [%4];" \
        : "=r"((r)[0]), "=r"((r)[1]), "=r"((r)[2]), "=r"((r)[3]) : "r"(addr))

__device__ __forceinline__ __half2 splitHi(float x, float y) {
    return __halves2half2(__float2half(x), __float2half(y));
}
__device__ __forceinline__ __half2 splitLo(float x, float y) {
    float hx = __half2float(__float2half(x)), hy = __half2float(__float2half(y));
    return __halves2half2(__float2half((x - hx) * 1024.0f),
                          __float2half((y - hy) * 1024.0f));
}
__device__ __forceinline__ uint32_t packh(float x, float y) {
    __half2 h = __halves2half2(__float2half(x), __float2half(y));
    return *reinterpret_cast<uint32_t*>(&h);
}

// ---------------- fused prep: 4 sections of 1024 blocks ----------------
__global__ __launch_bounds__(256) void prep_all(
    const float* __restrict__ x_mu, const float* __restrict__ y_eta,
    const float* __restrict__ y_mean, const float* __restrict__ y_var,
    const float* __restrict__ X_mean, const float* __restrict__ X_var,
    const float* __restrict__ Zm, const float* __restrict__ Zv,
    float* __restrict__ out)
{
    int sec = blockIdx.x >> 10, bx = blockIdx.x & 1023;
    int lane = threadIdx.x & 31;
    if (sec == 0) {
        int q = bx * 8 + (threadIdx.x >> 5);
        float a = x_mu[q * 32 + lane];
        float s = y_mean[q * 32 + lane] + y_var[q * 32 + lane];
        float e = 0.01f * y_eta[(NQ - 1 - q) * 32 + lane];
        g_qmh[q * 64 + lane] = __float2half(a);
        g_qmh[q * 64 + 32 + lane] = __float2half(s);
        g_qvh[q * 96 + lane] = __float2half(a);
        g_qvh[q * 96 + 32 + lane] = __float2half(e);
        g_qvh[q * 96 + 64 + lane] = __float2half(s);
        out[q * 32 + lane] = s;
        float nm = a * a + s * s, nv = nm + e * e;
#pragma unroll
        for (int o = 16; o > 0; o >>= 1) {
            nm += __shfl_xor_sync(~0u, nm, o);
            nv += __shfl_xor_sync(~0u, nv, o);
        }
        if (lane == 0) {
            g_eqm[q] = __expf(-nm * 0.0078125f);
            g_eqv[q] = __expf(-nv * 0.0078125f);
        }
    } else if (sec == 1) {
        int n = bx * 8 + (threadIdx.x >> 5);
        float acc = 0.0f;
#pragma unroll
        for (int d = 0; d < 64; d += 32) {
            float v = X_mean[(size_t)n * 64 + d + lane];
            g_Xmh[(size_t)n * 64 + d + lane] = __float2half(v);
            acc = fmaf(v, v, acc);
        }
#pragma unroll
        for (int o = 16; o > 0; o >>= 1) acc += __shfl_xor_sync(~0u, acc, o);
        if (lane == 0) g_exnm[n] = __expf(-acc * 0.0078125f);
    } else if (sec == 2) {
        int n = bx * 8 + (threadIdx.x >> 5);
        float acc = 0.0f;
#pragma unroll
        for (int d = 0; d < 96; d += 32) {
            float v = X_var[(size_t)n * 96 + d + lane];
            g_Xvh[(size_t)n * 96 + d + lane] = __float2half(v);
            acc = fmaf(v, v, acc);
        }
#pragma unroll
        for (int o = 16; o > 0; o >>= 1) acc += __shfl_xor_sync(~0u, acc, o);
        if (lane == 0) g_exnv[n] = __expf(-acc * 0.0078125f);
    } else {
        int o = bx * 256 + threadIdx.x;
        int j = o >> 13, n = o & (NQ - 1);
        float zm = Zm[n * 32 + j], zv = Zv[n * 32 + j];
        g_ZTh[0][o] = __low2half(splitHi(zm, zm)); g_ZTl[0][o] = __low2half(splitLo(zm, zm));
        g_ZTh[1][o] = __low2half(splitHi(zv, zv)); g_ZTl[1][o] = __low2half(splitLo(zv, zv));
        g_L[0][o] = 0.0f; g_L[1][o] = 0.0f;
    }
}

__global__ __launch_bounds__(256) void scaleL()
{
    int o = blockIdx.x * 256 + threadIdx.x;
    int j = o >> 13, n = o & (NQ - 1);
    float a = g_L[0][n * 32 + j] * g_exnm[n];
    float b = g_L[1][n * 32 + j] * g_exnv[n];
    g_LTh[0][o] = __low2half(splitHi(a, a)); g_LTl[0][o] = __low2half(splitLo(a, a));
    g_LTh[1][o] = __low2half(splitHi(b, b)); g_LTl[1][o] = __low2half(splitLo(b, b));
}

// ---------------- Stage A: Lambda = kXX_inv @ Z  (fp16 2-term: Ah*(Zh+Zl)) ----------------
template <int V>
__global__ __launch_bounds__(256, 2) void stageA(const float* __restrict__ A)
{
    extern __shared__ char smA[];
    float*  sAf = (float*)smA;                           // [2][128*36]
    __half* sAh = (__half*)(smA + 36864);                // [2][128*40]
    __half* sZh = (__half*)(smA + 36864 + 20480);        // [2][32*40]
    __half* sZl = sZh + 2 * 32 * 40;
    int tid = threadIdx.x, wid = tid >> 5, lane = tid & 31;
    int g = lane >> 2, kq = lane & 3;
    size_t r0 = (size_t)blockIdx.x * 128;
    int kb = blockIdx.y * 2048;
    uint32_t aAf = sm_u32(sAf), aZh = sm_u32(sZh), aZl = sm_u32(sZl);

    auto load = [&](int c) {
        int b = c & 1, kc = kb + c * 32;
#pragma unroll
        for (int t = 0; t < 4; t++) {
            int f = tid + 256 * t, r = f >> 3, kg = f & 7;
            cp16(aAf + (b * 128 * 36 + r * 36 + kg * 4) * 4,
                 A + (r0 + r) * NQ + kc + kg * 4);
        }
        {
            int h = tid >> 7, rem = tid & 127, j = rem >> 2, kg = rem & 3;
            const __half* src = h ? g_ZTl[V] : g_ZTh[V];
            cp16((h ? aZl : aZh) + (b * 32 * 40 + j * 40 + kg * 8) * 2,
                 src + (size_t)j * NQ + kc + kg * 8);
        }
        CPC();
    };
    load(0);

    float accH[4][4], accL[4][4];
#pragma unroll
    for (int i = 0; i < 4; i++)
#pragma unroll
        for (int j = 0; j < 4; j++) { accH[i][j] = 0.0f; accL[i][j] = 0.0f; }

    for (int c = 0; c < 64; c++) {
        int b = c & 1;
        if (c + 1 < 64) { load(c + 1); CPW(1); } else CPW(0);
        __syncthreads();
#pragma unroll
        for (int t = 0; t < 8; t++) {
            int idx = tid + 256 * t;
            int r = idx >> 4, kp = idx & 15;
            float2 v = *(float2*)&sAf[b * 128 * 36 + r * 36 + kp * 2];
            *(__half2*)&sAh[b * 128 * 40 + r * 40 + kp * 2] = splitHi(v.x, v.y);
        }
        __syncthreads();
        const __half* pAh = sAh + b * 128 * 40;
        const __half* pZh = sZh + b * 32 * 40;
        const __half* pZl = sZl + b * 32 * 40;
        int rA = wid * 16 + g;
#pragma unroll
        for (int ks = 0; ks < 2; ks++) {
            int ko = ks * 16 + 2 * kq;
            uint32_t ah[4];
            ah[0] = *(const uint32_t*)&pAh[rA * 40 + ko];
            ah[1] = *(const uint32_t*)&pAh[(rA + 8) * 40 + ko];
            ah[2] = *(const uint32_t*)&pAh[rA * 40 + ko + 8];
            ah[3] = *(const uint32_t*)&pAh[(rA + 8) * 40 + ko + 8];
#pragma unroll
            for (int nt = 0; nt < 4; nt++) {
                int rB = nt * 8 + g;
                uint32_t bh[2], bl[2];
                bh[0] = *(const uint32_t*)&pZh[rB * 40 + ko];
                bh[1] = *(const uint32_t*)&pZh[rB * 40 + ko + 8];
                bl[0] = *(const uint32_t*)&pZl[rB * 40 + ko];
                bl[1] = *(const uint32_t*)&pZl[rB * 40 + ko + 8];
                mma16(accH[nt], ah, bh);
                mma16(accL[nt], ah, bl);
            }
        }
        __syncthreads();
    }
    float* L = g_L[V];
    size_t ra = r0 + wid * 16 + g;
#pragma unroll
    for (int nt = 0; nt < 4; nt++) {
        int col = nt * 8 + 2 * kq;
        atomicAdd(&L[ra * 32 + col],           accH[nt][0] + accL[nt][0] * 9.765625e-4f);
        atomicAdd(&L[ra * 32 + col + 1],       accH[nt][1] + accL[nt][1] * 9.765625e-4f);
        atomicAdd(&L[(ra + 8) * 32 + col],     accH[nt][2] + accL[nt][2] * 9.765625e-4f);
        atomicAdd(&L[(ra + 8) * 32 + col + 1], accH[nt][3] + accL[nt][3] * 9.765625e-4f);
    }
}

// ---------------- Stage B: 256-q tiles, half the cp.async stream ----------------
// grid (32 q-tiles x 256, 8 n-splits x 1024), block 256, occ 2, 16 chunks of 64 n.
// Each warp owns 32 q rows x full 64 n, in two 32-n half-passes per chunk.
template <int D, int V>
__global__ __launch_bounds__(256, 2) void stageB(float* __restrict__ out)
{
    const __half* Qg = V ? g_qvh : g_qmh;
    const __half* Xg = V ? g_Xvh : g_Xmh;
    const float*  EQ = V ? g_eqv : g_eqm;
    extern __shared__ __half smB[];
    const int SP = D + 8;
    __half* sQ  = smB;                    // [256][SP]
    __half* sX  = sQ + 256 * SP;          // [2][64][SP]
    __half* sLh = sX + 2 * 64 * SP;       // [2][32 j][72 n]
    __half* sLl = sLh + 2 * 32 * 72;
    uint32_t aQ = sm_u32(sQ), aX = sm_u32(sX), aLh = sm_u32(sLh), aLl = sm_u32(sLl);
    int tid = threadIdx.x, w = tid >> 5, lane = tid & 31;
    int g = lane >> 2, kq = lane & 3;
    int q0 = blockIdx.x * 256, nb = blockIdx.y * 1024;
    const int NC = 16;
    const int XB = 64 * SP * 2, LB = 32 * 72 * 2;
    const int HX = 32 * SP * 2;           // X half-row offset (32 n rows)

    int m = lane >> 3, lr = lane & 7;
    uint32_t adrQ[2], adrX[2], adrLh[2], adrLl[2];
#pragma unroll
    for (int mt = 0; mt < 2; mt++) {
        int row = w * 32 + mt * 16 + (m & 1) * 8 + lr;
        adrQ[mt] = aQ + (row * SP) * 2 + (m >> 1) * 16;
    }
#pragma unroll
    for (int p = 0; p < 2; p++) {
        int n = (2 * p + (m >> 1)) * 8 + lr;
        adrX[p] = aX + (n * SP) * 2 + (m & 1) * 16;
        int j = (2 * p + (m >> 1)) * 8 + lr;
        uint32_t off = (j * 72) * 2 + (m & 1) * 16;
        adrLh[p] = aLh + off;
        adrLl[p] = aLl + off;
    }

    for (int idx = tid; idx < 256 * (D / 8); idx += 256) {
        int r = idx / (D / 8), kg = idx % (D / 8);
        cp16(aQ + (r * SP + kg * 8) * 2, Qg + (size_t)(q0 + r) * D + kg * 8);
    }
    auto loadC = [&](int c) {
        int b = c & 1, n0 = nb + c * 64;
        for (int idx = tid; idx < 64 * (D / 8); idx += 256) {
            int r = idx / (D / 8), kg = idx % (D / 8);
            cp16(aX + b * XB + (r * SP + kg * 8) * 2,
                 Xg + (size_t)(n0 + r) * D + kg * 8);
        }
#pragma unroll
        for (int t = 0; t < 2; t++) {
            int f = tid + 256 * t;
            int h = f >> 8, rem = f & 255, j = rem >> 3, kg = rem & 7;
            const __half* src = h ? g_LTl[V] : g_LTh[V];
            cp16((h ? aLl : aLh) + b * LB + (j * 72 + kg * 8) * 2,
                 src + (size_t)j * NQ + n0 + kg * 8);
        }
        CPC();
    };
    loadC(0);

    float zH[2][4][4];
#pragma unroll
    for (int mm = 0; mm < 2; mm++)
#pragma unroll
        for (int i = 0; i < 4; i++)
#pragma unroll
            for (int j = 0; j < 4; j++) zH[mm][i][j] = 0.0f;

    const float S10 = 9.765625e-4f;   // 2^-10

    for (int c = 0; c < NC; c++) {
        int b = c & 1;
        if (c + 1 < NC) { loadC(c + 1); CPW(1); } else CPW(0);
        __syncthreads();

#pragma unroll
        for (int half = 0; half < 2; half++) {
            uint32_t xoff = b * XB + half * HX;
            // mma1: S = Q . X^T for this warp's 32q x 32n half-tile
            float s[2][4][4];
#pragma unroll
            for (int mt = 0; mt < 2; mt++)
#pragma unroll
                for (int nt = 0; nt < 4; nt++)
#pragma unroll
                    for (int i = 0; i < 4; i++) s[mt][nt][i] = 0.0f;
#pragma unroll
            for (int ks = 0; ks < D / 16; ks++) {
                uint32_t a2[2][4], bb[2][4];
                LDSM4(a2[0], adrQ[0] + ks * 32);
                LDSM4(a2[1], adrQ[1] + ks * 32);
                LDSM4(bb[0], adrX[0] + xoff + ks * 32);
                LDSM4(bb[1], adrX[1] + xoff + ks * 32);
#pragma unroll
                for (int p = 0; p < 2; p++) {
                    mma16(s[0][2 * p],     a2[0], &bb[p][0]);
                    mma16(s[0][2 * p + 1], a2[0], &bb[p][2]);
                    mma16(s[1][2 * p],     a2[1], &bb[p][0]);
                    mma16(s[1][2 * p + 1], a2[1], &bb[p][2]);
                }
            }
            // K = exp(S/64); pack hi and scaled-lo A-fragments (k = n dim)
            uint32_t kh[2][2][4], kl[2][2][4];
#pragma unroll
            for (int mt = 0; mt < 2; mt++)
#pragma unroll
                for (int nt = 0; nt < 4; nt++)
#pragma unroll
                    for (int i = 0; i < 4; i++)
                        s[mt][nt][i] = __expf(s[mt][nt][i] * 0.015625f);
#pragma unroll
            for (int mt = 0; mt < 2; mt++)
#pragma unroll
                for (int ks = 0; ks < 2; ks++) {
                    kh[mt][ks][0] = packh(s[mt][2 * ks][0],     s[mt][2 * ks][1]);
                    kh[mt][ks][1] = packh(s[mt][2 * ks][2],     s[mt][2 * ks][3]);
                    kh[mt][ks][2] = packh(s[mt][2 * ks + 1][0], s[mt][2 * ks + 1][1]);
                    kh[mt][ks][3] = packh(s[mt][2 * ks + 1][2], s[mt][2 * ks + 1][3]);
                    kl[mt][ks][0] = packh(s[mt][2 * ks][0] * S10,     s[mt][2 * ks][1] * S10);
                    kl[mt][ks][1] = packh(s[mt][2 * ks][2] * S10,     s[mt][2 * ks][3] * S10);
                    kl[mt][ks][2] = packh(s[mt][2 * ks + 1][0] * S10, s[mt][2 * ks + 1][1] * S10);
                    kl[mt][ks][3] = packh(s[mt][2 * ks + 1][2] * S10, s[mt][2 * ks + 1][3] * S10);
                }

            // mma2: z += K . Lam'^T over this 32-n half (hi + scaled-lo into zH)
            uint32_t loff = b * LB + half * 64;
#pragma unroll
            for (int ks = 0; ks < 2; ks++) {
                uint32_t bh[2][4], bl[2][4];
                LDSM4(bh[0], adrLh[0] + loff + ks * 32);
                LDSM4(bh[1], adrLh[1] + loff + ks * 32);
                LDSM4(bl[0], adrLl[0] + loff + ks * 32);
                LDSM4(bl[1], adrLl[1] + loff + ks * 32);
#pragma unroll
                for (int jt = 0; jt < 4; jt++) {
                    int jp = jt >> 1, ji = (jt & 1) * 2;
                    mma16(zH[0][jt], kh[0][ks], &bh[jp][ji]);
                    mma16(zH[0][jt], kl[0][ks], &bl[jp][ji]);
                    mma16(zH[1][jt], kh[1][ks], &bh[jp][ji]);
                    mma16(zH[1][jt], kl[1][ks], &bl[jp][ji]);
                }
            }
        }
        __syncthreads();
    }
#pragma unroll
    for (int mt = 0; mt < 2; mt++) {
        int qa = q0 + w * 32 + mt * 16 + g;
        float e0 = EQ[qa], e1 = EQ[qa + 8];
#pragma unroll
        for (int jt = 0; jt < 4; jt++) {
            int col = jt * 8 + 2 * kq;
            atomicAdd(&out[qa * 32 + col],           e0 * zH[mt][jt][0]);
            atomicAdd(&out[qa * 32 + col + 1],       e0 * zH[mt][jt][1]);
            atomicAdd(&out[(qa + 8) * 32 + col],     e1 * zH[mt][jt][2]);
            atomicAdd(&out[(qa + 8) * 32 + col + 1], e1 * zH[mt][jt][3]);
        }
    }
}

// ---------------- launch ----------------
extern "C" void kernel_launch(void* const* d_in, const int* in_sizes, int n_in,
                              void* d_out, int out_size)
{
    const float* x_mu   = (const float*)d_in[0];
    const float* y_eta  = (const float*)d_in[1];
    const float* y_mean = (const float*)d_in[2];
    const float* y_var  = (const float*)d_in[3];
    const float* X_mean = (const float*)d_in[4];
    const float* X_var  = (const float*)d_in[5];
    const float* Z_mean = (const float*)d_in[6];
    const float* Z_var  = (const float*)d_in[7];
    const float* kXXm   = (const float*)d_in[8];
    const float* kXXv   = (const float*)d_in[9];
    float* out = (float*)d_out;

    const int SMA  = 36864 + 20480 + 2 * 5120;                         // 67584
    const int SMB0 = (256 * 72 + 2 * 64 * 72 + 4 * 32 * 72) * 2;       // 73728
    const int SMB1 = (256 * 104 + 2 * 64 * 104 + 4 * 32 * 72) * 2;     // 98304
    cudaFuncSetAttribute(stageA<0>, cudaFuncAttributeMaxDynamicSharedMemorySize, SMA);
    cudaFuncSetAttribute(stageA<1>, cudaFuncAttributeMaxDynamicSharedMemorySize, SMA);
    cudaFuncSetAttribute(stageB<64, 0>, cudaFuncAttributeMaxDynamicSharedMemorySize, SMB0);
    cudaFuncSetAttribute(stageB<96, 1>, cudaFuncAttributeMaxDynamicSharedMemorySize, SMB1);

    prep_all<<<4096, 256>>>(x_mu, y_eta, y_mean, y_var, X_mean, X_var,
                            Z_mean, Z_var, out);

    stageA<0><<<dim3(64, 4), 256, SMA>>>(kXXm);
    stageA<1><<<dim3(64, 4), 256, SMA>>>(kXXv);
    scaleL<<<1024, 256>>>();

    stageB<64, 0><<<dim3(32, 8), 256, SMB0>>>(out);
    stageB<96, 1><<<dim3(32, 8), 256, SMB1>>>(out);
}